// round 3
// baseline (speedup 1.0000x reference)
#include <cuda_runtime.h>

// Equivariant linear: RS = [(16,0),(16,1),(16,2)], dim = 144, BATCH = 262144.
// Block-diagonal per (l,m): out[z,l,v,t] = sum_u Wl[v,u] * x[z,l,u,t],
// Wl[v,u] = weight[l*256 + v*16 + u] * 0.25 / sqrt(2l+1).
// Row layout: l=0 cols [0,16) d=1; l=1 idx 16+u*3+t; l=2 idx 64+u*5+t.

#define ROWS_PER_BLOCK 32
#define ROW_STRIDE 145   // odd -> lane-stride conflict-free
#define NTHREADS 128
#define DIM 144
#define VECS_PER_ROW 36  // 144/4

__global__ __launch_bounds__(NTHREADS, 8) void eq_linear_kernel(
    const float* __restrict__ x,
    const float* __restrict__ w,
    float* __restrict__ y)
{
    __shared__ __align__(16) float sW[768];
    __shared__ float sD[ROWS_PER_BLOCK * ROW_STRIDE];

    const int tid  = threadIdx.x;
    const int lane = tid & 31;
    const int warp = tid >> 5;

    // Stage the three 16x16 mixing matrices, pre-scaled by cg * norm.
    // factor = 1/sqrt(256/16) = 0.25 ; cg = 1/sqrt(2l+1)
    #pragma unroll
    for (int i = tid; i < 768; i += NTHREADS) {
        int l = i >> 8;
        float scale = (l == 0) ? 0.25f
                    : (l == 1) ? 0.25f * 0.57735026918962576f   // 1/sqrt(3)
                               : 0.25f * 0.44721359549995794f;  // 1/sqrt(5)
        sW[i] = w[i] * scale;
    }

    const long long row0 = (long long)blockIdx.x * ROWS_PER_BLOCK;
    const float4* __restrict__ in4 =
        reinterpret_cast<const float4*>(x) + row0 * VECS_PER_ROW;

    // Coalesced tile load: 32 rows x 36 float4 = 1152 vec4, 9 per thread.
    #pragma unroll
    for (int i = tid; i < ROWS_PER_BLOCK * VECS_PER_ROW; i += NTHREADS) {
        int r = i / VECS_PER_ROW;
        int c = i % VECS_PER_ROW;
        float4 v = in4[(long long)r * VECS_PER_ROW + c];
        float* d = sD + r * ROW_STRIDE + c * 4;
        d[0] = v.x; d[1] = v.y; d[2] = v.z; d[3] = v.w;
    }
    __syncthreads();

    // Compute: 9 slices x 32 rows. warp handles slice s = it*4 + warp,
    // lane = row. W reads are warp-uniform float4 broadcasts.
    #pragma unroll
    for (int it = 0; it < 3; it++) {
        const int s = it * 4 + warp;
        if (s < 9) {
            int l, off, d;
            if (s == 0)      { l = 0; off = 0;            d = 1; }
            else if (s < 4)  { l = 1; off = 16 + (s - 1); d = 3; }
            else             { l = 2; off = 64 + (s - 4); d = 5; }

            float* p = sD + lane * ROW_STRIDE + off;

            float xv[16];
            #pragma unroll
            for (int u = 0; u < 16; u++) xv[u] = p[u * d];

            const float4* __restrict__ W4 =
                reinterpret_cast<const float4*>(sW + l * 256);
            float yv[16];
            #pragma unroll
            for (int v = 0; v < 16; v++) {
                float4 w0 = W4[v * 4 + 0];
                float4 w1 = W4[v * 4 + 1];
                float4 w2 = W4[v * 4 + 2];
                float4 w3 = W4[v * 4 + 3];
                float acc = 0.0f;
                acc = fmaf(w0.x, xv[0],  acc);
                acc = fmaf(w0.y, xv[1],  acc);
                acc = fmaf(w0.z, xv[2],  acc);
                acc = fmaf(w0.w, xv[3],  acc);
                acc = fmaf(w1.x, xv[4],  acc);
                acc = fmaf(w1.y, xv[5],  acc);
                acc = fmaf(w1.z, xv[6],  acc);
                acc = fmaf(w1.w, xv[7],  acc);
                acc = fmaf(w2.x, xv[8],  acc);
                acc = fmaf(w2.y, xv[9],  acc);
                acc = fmaf(w2.z, xv[10], acc);
                acc = fmaf(w2.w, xv[11], acc);
                acc = fmaf(w3.x, xv[12], acc);
                acc = fmaf(w3.y, xv[13], acc);
                acc = fmaf(w3.z, xv[14], acc);
                acc = fmaf(w3.w, xv[15], acc);
                yv[v] = acc;
            }

            #pragma unroll
            for (int v = 0; v < 16; v++) p[v * d] = yv[v];
        }
    }
    __syncthreads();

    // Coalesced store.
    float4* __restrict__ out4 =
        reinterpret_cast<float4*>(y) + row0 * VECS_PER_ROW;
    #pragma unroll
    for (int i = tid; i < ROWS_PER_BLOCK * VECS_PER_ROW; i += NTHREADS) {
        int r = i / VECS_PER_ROW;
        int c = i % VECS_PER_ROW;
        const float* d = sD + r * ROW_STRIDE + c * 4;
        out4[(long long)r * VECS_PER_ROW + c] = make_float4(d[0], d[1], d[2], d[3]);
    }
}

extern "C" void kernel_launch(void* const* d_in, const int* in_sizes, int n_in,
                              void* d_out, int out_size)
{
    const float* feat = (const float*)d_in[0];
    const float* w    = (const float*)d_in[1];
    float* out        = (float*)d_out;

    const int batch  = in_sizes[0] / DIM;        // 262144
    const int blocks = batch / ROWS_PER_BLOCK;   // 8192

    eq_linear_kernel<<<blocks, NTHREADS>>>(feat, w, out);
}

// round 4
// speedup vs baseline: 2.7086x; 2.7086x over previous
#include <cuda_runtime.h>

// Equivariant linear: RS = [(16,0),(16,1),(16,2)], dim = 144, BATCH = 262144.
// Block-diagonal per (l,m): out[z,l,v,t] = sum_u Wl[v,u] * x[z,l,u,t],
// Wl[v,u] = weight[l*256 + v*16 + u] * 0.25 / sqrt(2l+1).
// Row layout: l=0 cols [0,16) d=1; l=1 idx 16+u*3+t; l=2 idx 64+u*5+t.

#define ROWS 64
#define STRIDE 145      // odd -> lane-stride (row axis) conflict-free in smem
#define NT 128
#define DIM 144
#define V4 36           // 144/4

__global__ __launch_bounds__(NT, 5) void eq_linear_kernel(
    const float* __restrict__ x,
    const float* __restrict__ w,
    float* __restrict__ y)
{
    __shared__ __align__(16) float sWT[768];          // WT[l][u][v] (transposed, pre-scaled)
    __shared__ float sD[ROWS * STRIDE];

    const int tid  = threadIdx.x;
    const int lane = tid & 31;
    const int warp = tid >> 5;

    // Stage transposed, pre-scaled mixing matrices:
    // sWT[l*256 + u*16 + v] = weight[l*256 + v*16 + u] * 0.25/sqrt(2l+1)
    #pragma unroll
    for (int i = tid; i < 768; i += NT) {
        int l = i >> 8;
        int rem = i & 255;
        int u = rem >> 4;
        int v = rem & 15;
        float scale = (l == 0) ? 0.25f
                    : (l == 1) ? 0.25f * 0.57735026918962576f   // 1/sqrt(3)
                               : 0.25f * 0.44721359549995794f;  // 1/sqrt(5)
        sWT[i] = w[l * 256 + v * 16 + u] * scale;
    }

    const long long row0 = (long long)blockIdx.x * ROWS;
    const float4* __restrict__ in4 =
        reinterpret_cast<const float4*>(x) + row0 * V4;

    // Coalesced tile load: 64 rows x 36 float4, 18 per thread.
    #pragma unroll
    for (int i = tid; i < ROWS * V4; i += NT) {
        int r = i / V4;
        int c = i % V4;
        float4 v = in4[(long long)r * V4 + c];
        float* dst = sD + r * STRIDE + c * 4;
        dst[0] = v.x; dst[1] = v.y; dst[2] = v.z; dst[3] = v.w;
    }
    __syncthreads();

    // Compute: 9 slices; warp handles slice s = it*4 + warp, lane handles
    // rows {lane, lane+32}. Outer-product over u keeps live regs ~= 2x16 accs.
    #pragma unroll
    for (int it = 0; it < 3; it++) {
        const int s = it * 4 + warp;
        if (s < 9) {
            int l, off, d;
            if (s == 0)      { l = 0; off = 0;            d = 1; }
            else if (s < 4)  { l = 1; off = 16 + (s - 1); d = 3; }
            else             { l = 2; off = 64 + (s - 4); d = 5; }

            float* p0 = sD + lane * STRIDE + off;
            float* p1 = p0 + 32 * STRIDE;
            const float4* __restrict__ WT4 =
                reinterpret_cast<const float4*>(sWT + l * 256);

            float a0[16], a1[16];
            #pragma unroll
            for (int v = 0; v < 16; v++) { a0[v] = 0.0f; a1[v] = 0.0f; }

            #pragma unroll
            for (int u = 0; u < 16; u++) {
                float x0 = p0[u * d];
                float x1 = p1[u * d];
                #pragma unroll
                for (int q = 0; q < 4; q++) {
                    float4 wv = WT4[u * 4 + q];   // broadcast LDS.128
                    a0[q*4+0] = fmaf(wv.x, x0, a0[q*4+0]);
                    a0[q*4+1] = fmaf(wv.y, x0, a0[q*4+1]);
                    a0[q*4+2] = fmaf(wv.z, x0, a0[q*4+2]);
                    a0[q*4+3] = fmaf(wv.w, x0, a0[q*4+3]);
                    a1[q*4+0] = fmaf(wv.x, x1, a1[q*4+0]);
                    a1[q*4+1] = fmaf(wv.y, x1, a1[q*4+1]);
                    a1[q*4+2] = fmaf(wv.z, x1, a1[q*4+2]);
                    a1[q*4+3] = fmaf(wv.w, x1, a1[q*4+3]);
                }
            }

            #pragma unroll
            for (int v = 0; v < 16; v++) {
                p0[v * d] = a0[v];
                p1[v * d] = a1[v];
            }
        }
    }
    __syncthreads();

    // Coalesced store.
    float4* __restrict__ out4 =
        reinterpret_cast<float4*>(y) + row0 * V4;
    #pragma unroll
    for (int i = tid; i < ROWS * V4; i += NT) {
        int r = i / V4;
        int c = i % V4;
        const float* src = sD + r * STRIDE + c * 4;
        out4[(long long)r * V4 + c] = make_float4(src[0], src[1], src[2], src[3]);
    }
}

extern "C" void kernel_launch(void* const* d_in, const int* in_sizes, int n_in,
                              void* d_out, int out_size)
{
    const float* feat = (const float*)d_in[0];
    const float* w    = (const float*)d_in[1];
    float* out        = (float*)d_out;

    const int batch  = in_sizes[0] / DIM;   // 262144
    const int blocks = batch / ROWS;        // 4096

    eq_linear_kernel<<<blocks, NT>>>(feat, w, out);
}

// round 5
// speedup vs baseline: 4.7759x; 1.7632x over previous
#include <cuda_runtime.h>

// Equivariant linear: RS = [(16,0),(16,1),(16,2)], dim = 144, BATCH = 262144.
// Block-diagonal per (l,m): out[z,l,v,t] = sum_u Wl[v,u] * x[z,l,u,t],
// Wl[v,u] = weight[l*256 + v*16 + u] * 0.25 / sqrt(2l+1).
// Row layout: l=0 cols [0,16) d=1; l=1 idx 16+u*3+t (t=0..2); l=2 idx 64+u*5+t.

#define ROWS 32
#define STRIDE 145      // 145 mod 32 = 17, coprime -> row-axis conflict-free
#define NT 288          // 9 warps = 9 m-slices
#define DIM 144
#define V4 36           // 144/4

__global__ __launch_bounds__(NT) void eq_linear_kernel(
    const float* __restrict__ x,
    const float* __restrict__ w,
    float* __restrict__ y)
{
    __shared__ __align__(16) float sWT[768];   // WT[l][u][v], pre-scaled
    __shared__ float sD[ROWS * STRIDE];

    const int tid  = threadIdx.x;
    const int lane = tid & 31;
    const int s    = tid >> 5;      // warp id == slice id, 0..8

    // Stage transposed, pre-scaled mixing matrices:
    // sWT[l*256 + u*16 + v] = weight[l*256 + v*16 + u] * 0.25/sqrt(2l+1)
    for (int i = tid; i < 768; i += NT) {
        int l = i >> 8;
        int rem = i & 255;
        int u = rem >> 4;
        int v = rem & 15;
        float scale = (l == 0) ? 0.25f
                    : (l == 1) ? 0.25f * 0.57735026918962576f   // 1/sqrt(3)
                               : 0.25f * 0.44721359549995794f;  // 1/sqrt(5)
        sWT[i] = w[l * 256 + v * 16 + u] * scale;
    }

    const long long row0 = (long long)blockIdx.x * ROWS;
    const float4* __restrict__ in4 =
        reinterpret_cast<const float4*>(x) + row0 * V4;

    // Coalesced tile load: 32 rows x 36 float4 = 1152 = 4 per thread.
    #pragma unroll
    for (int k = 0; k < 4; k++) {
        int i = tid + k * NT;
        int r = i / V4;
        int c = i % V4;
        float4 v = in4[(long long)r * V4 + c];
        float* dst = sD + r * STRIDE + c * 4;
        dst[0] = v.x; dst[1] = v.y; dst[2] = v.z; dst[3] = v.w;
    }
    __syncthreads();

    // Compute: warp s owns slice s, lane owns row. Columns touched are
    // disjoint per slice, so in-place update needs no extra sync.
    {
        int l, off, d;
        if (s == 0)      { l = 0; off = 0;            d = 1; }
        else if (s < 4)  { l = 1; off = 16 + (s - 1); d = 3; }
        else             { l = 2; off = 64 + (s - 4); d = 5; }

        float* p = sD + lane * STRIDE + off;
        const float4* __restrict__ WT4 =
            reinterpret_cast<const float4*>(sWT + l * 256);

        float a[16];
        #pragma unroll
        for (int v = 0; v < 16; v++) a[v] = 0.0f;

        #pragma unroll
        for (int u = 0; u < 16; u++) {
            float xu = p[u * d];               // conflict-free scalar LDS
            #pragma unroll
            for (int q = 0; q < 4; q++) {
                float4 wv = WT4[u * 4 + q];    // warp-uniform LDS.128
                a[q*4+0] = fmaf(wv.x, xu, a[q*4+0]);
                a[q*4+1] = fmaf(wv.y, xu, a[q*4+1]);
                a[q*4+2] = fmaf(wv.z, xu, a[q*4+2]);
                a[q*4+3] = fmaf(wv.w, xu, a[q*4+3]);
            }
        }

        #pragma unroll
        for (int v = 0; v < 16; v++) p[v * d] = a[v];
    }
    __syncthreads();

    // Coalesced store.
    float4* __restrict__ out4 =
        reinterpret_cast<float4*>(y) + row0 * V4;
    #pragma unroll
    for (int k = 0; k < 4; k++) {
        int i = tid + k * NT;
        int r = i / V4;
        int c = i % V4;
        const float* src = sD + r * STRIDE + c * 4;
        out4[(long long)r * V4 + c] = make_float4(src[0], src[1], src[2], src[3]);
    }
}

extern "C" void kernel_launch(void* const* d_in, const int* in_sizes, int n_in,
                              void* d_out, int out_size)
{
    const float* feat = (const float*)d_in[0];
    const float* w    = (const float*)d_in[1];
    float* out        = (float*)d_out;

    const int batch  = in_sizes[0] / DIM;   // 262144
    const int blocks = batch / ROWS;        // 8192

    eq_linear_kernel<<<blocks, NT>>>(feat, w, out);
}

// round 6
// speedup vs baseline: 5.4160x; 1.1340x over previous
#include <cuda_runtime.h>

// Equivariant linear: RS = [(16,0),(16,1),(16,2)], dim = 144, BATCH = 262144.
// Block-diagonal per (l,m): out[z,l,v,t] = sum_u Wl[v,u] * x[z,l,u,t],
// Wl[v,u] = weight[l*256 + v*16 + u] * 0.25 / sqrt(2l+1).
// Row layout: l=0 cols [0,16) d=1; l=1 idx 16+u*3+t; l=2 idx 64+u*5+t.

#define ROWS 64
#define STRIDE 145      // odd -> row-axis scalar gather conflict-free
#define NT 288          // 9 warps = 9 m-slices
#define DIM 144
#define SCAL_PER_T 32   // 64*144 / 288

typedef unsigned long long ull;

__device__ __forceinline__ ull pack_dup(float x) {
    ull r;
    asm("mov.b64 %0, {%1, %1};" : "=l"(r) : "f"(x));
    return r;
}
__device__ __forceinline__ void ffma2(ull& acc, ull w2, ull x2) {
    asm("fma.rn.f32x2 %0, %1, %2, %0;" : "+l"(acc) : "l"(w2), "l"(x2));
}
__device__ __forceinline__ void unpack2(ull p, float& lo, float& hi) {
    asm("mov.b64 {%0, %1}, %2;" : "=f"(lo), "=f"(hi) : "l"(p));
}

__global__ __launch_bounds__(NT) void eq_linear_kernel(
    const float* __restrict__ x,
    const float* __restrict__ w,
    float* __restrict__ y)
{
    __shared__ __align__(16) float sWT[768];   // WT[l][u][v], pre-scaled
    __shared__ float sD[ROWS * STRIDE];

    const int tid  = threadIdx.x;
    const int lane = tid & 31;
    const int s    = tid >> 5;      // warp id == slice id, 0..8

    // Stage transposed, pre-scaled mixing matrices:
    // sWT[l*256 + u*16 + v] = weight[l*256 + v*16 + u] * 0.25/sqrt(2l+1)
    for (int i = tid; i < 768; i += NT) {
        int l = i >> 8;
        int rem = i & 255;
        int u = rem >> 4;
        int v = rem & 15;
        float scale = (l == 0) ? 0.25f
                    : (l == 1) ? 0.25f * 0.57735026918962576f   // 1/sqrt(3)
                               : 0.25f * 0.44721359549995794f;  // 1/sqrt(5)
        sWT[i] = w[l * 256 + v * 16 + u] * scale;
    }

    const long long row0 = (long long)blockIdx.x * ROWS;

    // Coalesced scalar tile load. Thread owns fixed column c = tid % 144,
    // rows rb + 2k -> consecutive lanes hit consecutive floats (1 wf/instr),
    // STS likewise conflict-free (addresses consecutive mod the row seam).
    {
        const int c  = tid % DIM;
        const int rb = tid / DIM;               // 0 or 1
        const float* __restrict__ gsrc = x + (row0 + rb) * DIM + c;
        float*       ssrc = sD + rb * STRIDE + c;
        #pragma unroll 8
        for (int k = 0; k < SCAL_PER_T; k++) {
            ssrc[(2 * k) * STRIDE] = gsrc[(long long)(2 * k) * DIM];
        }
    }
    __syncthreads();

    // Compute: warp s owns slice s; lane owns rows {lane, lane+32}.
    // v-pair-packed f32x2 FMAs: acc{2j,2j+1} += {w_2j, w_2j+1} * {x, x}.
    {
        int l, off, d;
        if (s == 0)      { l = 0; off = 0;            d = 1; }
        else if (s < 4)  { l = 1; off = 16 + (s - 1); d = 3; }
        else             { l = 2; off = 64 + (s - 4); d = 5; }

        float* p0 = sD + lane * STRIDE + off;
        float* p1 = p0 + 32 * STRIDE;
        const ulonglong2* __restrict__ WT =
            reinterpret_cast<const ulonglong2*>(sWT + l * 256);

        ull a0[8], a1[8];
        #pragma unroll
        for (int j = 0; j < 8; j++) { a0[j] = 0ull; a1[j] = 0ull; }

        #pragma unroll
        for (int u = 0; u < 16; u++) {
            ull xd0 = pack_dup(p0[u * d]);     // conflict-free scalar LDS
            ull xd1 = pack_dup(p1[u * d]);
            #pragma unroll
            for (int q = 0; q < 4; q++) {
                ulonglong2 wp = WT[u * 4 + q]; // warp-uniform LDS.128 = 4 w's
                ffma2(a0[2*q+0], wp.x, xd0);
                ffma2(a0[2*q+1], wp.y, xd0);
                ffma2(a1[2*q+0], wp.x, xd1);
                ffma2(a1[2*q+1], wp.y, xd1);
            }
        }

        #pragma unroll
        for (int j = 0; j < 8; j++) {
            float lo, hi;
            unpack2(a0[j], lo, hi);
            p0[(2*j+0) * d] = lo;
            p0[(2*j+1) * d] = hi;
            unpack2(a1[j], lo, hi);
            p1[(2*j+0) * d] = lo;
            p1[(2*j+1) * d] = hi;
        }
    }
    __syncthreads();

    // Coalesced scalar store (mirror of the load).
    {
        const int c  = tid % DIM;
        const int rb = tid / DIM;
        float* __restrict__ gdst = y + (row0 + rb) * DIM + c;
        const float* sdst = sD + rb * STRIDE + c;
        #pragma unroll 8
        for (int k = 0; k < SCAL_PER_T; k++) {
            gdst[(long long)(2 * k) * DIM] = sdst[(2 * k) * STRIDE];
        }
    }
}

extern "C" void kernel_launch(void* const* d_in, const int* in_sizes, int n_in,
                              void* d_out, int out_size)
{
    const float* feat = (const float*)d_in[0];
    const float* w    = (const float*)d_in[1];
    float* out        = (float*)d_out;

    const int batch  = in_sizes[0] / DIM;   // 262144
    const int blocks = batch / ROWS;        // 4096

    eq_linear_kernel<<<blocks, NT>>>(feat, w, out);
}